// round 3
// baseline (speedup 1.0000x reference)
#include <cuda_runtime.h>
#include <cstdint>
#include <cstddef>

#define L_STEPS 32768
#define N_IN    300
#define N_H     512
#define N_G     2048      // 4*N_H
#define N_WORK  128       // worker CTAs
#define PNET_C  1624      // 2H + 2I

// ------------------------- device scratch (static) -------------------------
__device__ __align__(16) float g_xproj[(size_t)L_STEPS * N_G];   // 256 MB
__device__ float g_polbase[L_STEPS * 2];
__device__ __align__(16) float g_aemb[N_IN];
__device__ float g_apol[2];
__device__ __align__(16) float g_h[2][N_H];
__device__ __align__(16) float g_c[2][N_H];
__device__ unsigned g_cnt[L_STEPS];
__device__ int g_act[L_STEPS];
__device__ int g_retain;

// ------------------------- threefry2x32 (exact JAX) ------------------------
__device__ __forceinline__ uint32_t rotl32(uint32_t x, int r) {
    return (x << r) | (x >> (32 - r));
}
__device__ __forceinline__ void tf2(uint32_t k0, uint32_t k1,
                                    uint32_t x0, uint32_t x1,
                                    uint32_t& o0, uint32_t& o1) {
    uint32_t k2 = k0 ^ k1 ^ 0x1BD11BDAu;
    x0 += k0; x1 += k1;
#define R1(r) { x0 += x1; x1 = rotl32(x1, r); x1 ^= x0; }
#define R4(a,b,c,d) R1(a) R1(b) R1(c) R1(d)
    R4(13,15,26,6)   x0 += k1; x1 += k2 + 1u;
    R4(17,29,16,24)  x0 += k2; x1 += k0 + 2u;
    R4(13,15,26,6)   x0 += k0; x1 += k1 + 3u;
    R4(17,29,16,24)  x0 += k1; x1 += k2 + 4u;
    R4(13,15,26,6)   x0 += k2; x1 += k0 + 5u;
#undef R4
#undef R1
    o0 = x0; o1 = x1;
}

__device__ __forceinline__ float gumbel_from_bits(uint32_t bits) {
    // JAX: uniform(tiny, 1) then -log(-log(u))
    uint32_t fb = (bits >> 9) | 0x3f800000u;
    float u = __uint_as_float(fb) - 1.0f;          // [0,1)
    const float TINY = 1.17549435e-38f;
    float uu = fmaxf(TINY, __fadd_rn(u, TINY));    // u*(1-tiny)+tiny with (1-tiny)==1
    return -logf(-logf(uu));
}

// ------------------------- sync primitives ---------------------------------
__device__ __forceinline__ unsigned ld_acq_u(const unsigned* p) {
    unsigned v;
    asm volatile("ld.acquire.gpu.u32 %0, [%1];" : "=r"(v) : "l"(p) : "memory");
    return v;
}
__device__ __forceinline__ int ld_acq_s(const int* p) {
    int v;
    asm volatile("ld.acquire.gpu.s32 %0, [%1];" : "=r"(v) : "l"(p) : "memory");
    return v;
}
__device__ __forceinline__ void st_rel_s(int* p, int v) {
    asm volatile("st.release.gpu.s32 [%0], %1;" :: "l"(p), "r"(v) : "memory");
}
__device__ __forceinline__ void atom_add_rel_u(unsigned* p, unsigned v) {
    unsigned old;
    asm volatile("atom.add.release.gpu.u32 %0, [%1], %2;"
                 : "=r"(old) : "l"(p), "r"(v) : "memory");
}

__device__ __forceinline__ float warp_sum(float v) {
#pragma unroll
    for (int o = 16; o; o >>= 1) v += __shfl_xor_sync(0xffffffffu, v, o);
    return v;
}

__device__ __forceinline__ float sigm(float x) {
    // XLA logistic: 0.5 + 0.5*tanh(0.5*x)
    return 0.5f + 0.5f * tanhf(0.5f * x);
}

// ------------------------- init: zero state --------------------------------
__global__ void k_init() {
    int i = blockIdx.x * blockDim.x + threadIdx.x;
    int stride = gridDim.x * blockDim.x;
    for (int k = i; k < L_STEPS; k += stride) { g_cnt[k] = 0u; g_act[k] = 0; }
    for (int k = i; k < N_H; k += stride) {
        g_h[0][k] = 0.0f; g_h[1][k] = 0.0f;
        g_c[0][k] = 0.0f; g_c[1][k] = 0.0f;
    }
}

// ------------------------- a_emb + aspect part of policy logits ------------
__global__ void k_aemb(const long long* __restrict__ aspect,
                       const float* __restrict__ AE_w,
                       const float* __restrict__ pnet_W,
                       const float* __restrict__ pnet_b) {
    int tid = threadIdx.x;
    long long a = aspect[0];
    if (tid < N_IN) g_aemb[tid] = AE_w[(size_t)a * N_IN + tid];
    __syncthreads();
    int w = tid >> 5, lane = tid & 31;
    if (w < 2) {
        float s = 0.0f;
        for (int k = lane; k < N_IN; k += 32)
            s += g_aemb[k] * pnet_W[(size_t)w * PNET_C + 1324 + k];
        s = warp_sum(s);
        if (lane == 0) g_apol[w] = s + pnet_b[w];
    }
}

// ------------------------- per-step policy base: x-dot + gumbel ------------
__global__ void __launch_bounds__(256) k_polbase(const float* __restrict__ X,
                                                 const float* __restrict__ pnet_W) {
    int w = threadIdx.x >> 5, lane = threadIdx.x & 31;
    int t = blockIdx.x * 8 + w;
    const float* x = X + (size_t)t * N_IN;
    float d0 = 0.0f, d1 = 0.0f;
    for (int k = lane; k < N_IN; k += 32) {
        float xv = x[k];
        d0 += xv * pnet_W[1024 + k];
        d1 += xv * pnet_W[PNET_C + 1024 + k];
    }
    d0 = warp_sum(d0);
    d1 = warp_sum(d1);
    if (lane == 0) {
        // partitionable threefry: subkey_t = tf(key, (0, t)), both words kept
        uint32_t s0, s1; tf2(0u, 42u, 0u, (uint32_t)t, s0, s1);
        // partitionable random_bits (32-bit): bits_j = y0 ^ y1 of lane (0, j)
        uint32_t y0, y1;
        tf2(s0, s1, 0u, 0u, y0, y1);
        float gum0 = gumbel_from_bits(y0 ^ y1);
        tf2(s0, s1, 0u, 1u, y0, y1);
        float gum1 = gumbel_from_bits(y0 ^ y1);
        g_polbase[t * 2 + 0] = d0 + g_apol[0] + gum0;
        g_polbase[t * 2 + 1] = d1 + g_apol[1] + gum1;
    }
}

// ------------------------- GEMM: xproj = X @ W_ih^T + b_ih -----------------
#define GBM 128
#define GBN 128
#define GBK 12
__global__ void __launch_bounds__(256) k_gemm(const float* __restrict__ X,
                                              const float* __restrict__ W,
                                              const float* __restrict__ bih) {
    __shared__ __align__(16) float Xs[GBK][GBM];
    __shared__ __align__(16) float Ws[GBK][GBN];
    int tb = blockIdx.y * GBM;     // t tile
    int rb = blockIdx.x * GBN;     // row tile
    int tid = threadIdx.x;
    int tx = tid & 15, ty = tid >> 4;
    float acc[8][8] = {};
    for (int k0 = 0; k0 < N_IN; k0 += GBK) {
        for (int i = tid; i < GBM * GBK; i += 256) {
            int kk = i % GBK, m = i / GBK;
            Xs[kk][m] = X[(size_t)(tb + m) * N_IN + k0 + kk];
            Ws[kk][m] = W[(size_t)(rb + m) * N_IN + k0 + kk];
        }
        __syncthreads();
#pragma unroll
        for (int kk = 0; kk < GBK; kk++) {
            float xv[8], wv[8];
            *(float4*)&xv[0] = *(const float4*)&Xs[kk][ty * 8];
            *(float4*)&xv[4] = *(const float4*)&Xs[kk][ty * 8 + 4];
            *(float4*)&wv[0] = *(const float4*)&Ws[kk][tx * 8];
            *(float4*)&wv[4] = *(const float4*)&Ws[kk][tx * 8 + 4];
#pragma unroll
            for (int i = 0; i < 8; i++)
#pragma unroll
                for (int j = 0; j < 8; j++)
                    acc[i][j] += xv[i] * wv[j];
        }
        __syncthreads();
    }
#pragma unroll
    for (int i = 0; i < 8; i++) {
        int t = tb + ty * 8 + i;
#pragma unroll
        for (int j = 0; j < 8; j += 4) {
            int r = rb + tx * 8 + j;
            float4 o;
            o.x = acc[i][j + 0] + bih[r + 0];
            o.y = acc[i][j + 1] + bih[r + 1];
            o.z = acc[i][j + 2] + bih[r + 2];
            o.w = acc[i][j + 3] + bih[r + 3];
            *(float4*)(g_xproj + (size_t)t * N_G + r) = o;
        }
    }
}

// ------------------------- sequential phase --------------------------------
// 129 CTAs x 128 threads (co-resident; grid <= SM count).
// CTA c < 128: owns hidden units [4c, 4c+4). Warp w computes gate w for all
// 4 units with register-resident W_hh rows. CTA 128: policy.
__global__ void __launch_bounds__(128, 1) k_seq(const float* __restrict__ W_hh,
                                                const float* __restrict__ b_hh,
                                                const float* __restrict__ pnet_W) {
    int tid = threadIdx.x;
    int cta = blockIdx.x;

    if (cta < N_WORK) {
        // ---------------- worker ----------------
        int w = tid >> 5, lane = tid & 31;
        int unit0 = cta * 4;
        int rowbase = w * 512 + unit0;          // first of 4 consecutive gate rows

        float wreg[4][16];
#pragma unroll
        for (int j = 0; j < 4; j++) {
            const float4* src =
                (const float4*)(W_hh + (size_t)(rowbase + j) * N_H + lane * 16);
#pragma unroll
            for (int q = 0; q < 4; q++) {
                float4 v = src[q];
                wreg[j][q * 4 + 0] = v.x; wreg[j][q * 4 + 1] = v.y;
                wreg[j][q * 4 + 2] = v.z; wreg[j][q * 4 + 3] = v.w;
            }
        }
        float4 bhh = *(const float4*)(b_hh + rowbase);

        __shared__ __align__(16) float hs[N_H];
        __shared__ float gsm[16];
        __shared__ int sact;

        float h_cur = 0.0f, c_cur = 0.0f;       // valid for tid < 4

        for (int t = 0; t < L_STEPS; t++) {
            int cur = t & 1, nxt = cur ^ 1;
            if (t > 0) {
                if (tid == 0) {
                    while (ld_acq_u(&g_cnt[t - 1]) < (unsigned)N_WORK) { }
                }
                __syncthreads();
            }
            // broadcast h into smem
            ((float4*)hs)[tid] = ((const float4*)g_h[cur])[tid];
            __syncthreads();

            // register matvec: 4 rows x 16 weights per lane
            float acc0 = 0.f, acc1 = 0.f, acc2 = 0.f, acc3 = 0.f;
#pragma unroll
            for (int q = 0; q < 4; q++) {
                float4 hv = ((const float4*)hs)[lane * 4 + q];
                acc0 += wreg[0][q*4+0]*hv.x + wreg[0][q*4+1]*hv.y + wreg[0][q*4+2]*hv.z + wreg[0][q*4+3]*hv.w;
                acc1 += wreg[1][q*4+0]*hv.x + wreg[1][q*4+1]*hv.y + wreg[1][q*4+2]*hv.z + wreg[1][q*4+3]*hv.w;
                acc2 += wreg[2][q*4+0]*hv.x + wreg[2][q*4+1]*hv.y + wreg[2][q*4+2]*hv.z + wreg[2][q*4+3]*hv.w;
                acc3 += wreg[3][q*4+0]*hv.x + wreg[3][q*4+1]*hv.y + wreg[3][q*4+2]*hv.z + wreg[3][q*4+3]*hv.w;
            }
            acc0 = warp_sum(acc0); acc1 = warp_sum(acc1);
            acc2 = warp_sum(acc2); acc3 = warp_sum(acc3);

            if (lane == 0) {
                float4 xb = *(const float4*)(g_xproj + (size_t)t * N_G + rowbase);
                gsm[w * 4 + 0] = (xb.x + acc0) + bhh.x;
                gsm[w * 4 + 1] = (xb.y + acc1) + bhh.y;
                gsm[w * 4 + 2] = (xb.z + acc2) + bhh.z;
                gsm[w * 4 + 3] = (xb.w + acc3) + bhh.w;
            }
            __syncthreads();

            float cc = 0.0f, hh2 = 0.0f;
            if (tid < 4) {
                float gi = gsm[tid], gf = gsm[4 + tid];
                float gg = gsm[8 + tid], go = gsm[12 + tid];
                float si = sigm(gi), sf = sigm(gf), so = sigm(go);
                float tg = tanhf(gg);
                cc = sf * c_cur + si * tg;
                hh2 = so * tanhf(cc);
            }

            // wait for policy action
            if (tid == 0) {
                int a;
                do { a = ld_acq_s(&g_act[t]); } while (a == 0);
                sact = a;
            }
            __syncthreads();

            if (tid < 4) {
                if (sact == 2) { c_cur = cc; h_cur = hh2; }
                g_h[nxt][unit0 + tid] = h_cur;
                g_c[nxt][unit0 + tid] = c_cur;
                __threadfence();
            }
            __syncthreads();
            if (tid == 0) atom_add_rel_u(&g_cnt[t], 1u);
        }
    } else {
        // ---------------- policy ----------------
        int lane = tid & 31, w = tid >> 5;
        float wc[2][4], wh[2][4];
#pragma unroll
        for (int j = 0; j < 2; j++)
#pragma unroll
            for (int m = 0; m < 4; m++) {
                wc[j][m] = pnet_W[(size_t)j * PNET_C + tid + 128 * m];
                wh[j][m] = pnet_W[(size_t)j * PNET_C + 512 + tid + 128 * m];
            }
        __shared__ float part[8];
        int retain = 0;

        for (int t = 0; t < L_STEPS; t++) {
            int cur = t & 1;
            if (t > 0) {
                if (tid == 0) {
                    while (ld_acq_u(&g_cnt[t - 1]) < (unsigned)N_WORK) { }
                }
                __syncthreads();
            }
            float a0 = 0.0f, a1 = 0.0f;
#pragma unroll
            for (int m = 0; m < 4; m++) {
                float cv = g_c[cur][tid + 128 * m];
                float hv = g_h[cur][tid + 128 * m];
                a0 += wc[0][m] * cv + wh[0][m] * hv;
                a1 += wc[1][m] * cv + wh[1][m] * hv;
            }
            a0 = warp_sum(a0);
            a1 = warp_sum(a1);
            if (lane == 0) { part[w * 2 + 0] = a0; part[w * 2 + 1] = a1; }
            __syncthreads();
            if (tid == 0) {
                float l0 = (part[0] + part[2] + part[4] + part[6]) + g_polbase[t * 2 + 0];
                float l1 = (part[1] + part[3] + part[5] + part[7]) + g_polbase[t * 2 + 1];
                int act = (l1 > l0) ? 2 : 1;   // argmax tie -> index 0 (skip)
                retain += (act == 2);
                st_rel_s(&g_act[t], act);
            }
            __syncthreads();
        }
        if (tid == 0) g_retain = retain;
    }
}

// ------------------------- final: decoded + retain -------------------------
__global__ void k_final(const float* __restrict__ dec_W,
                        const float* __restrict__ dec_b,
                        float* __restrict__ out, int out_size) {
    __shared__ float dec[3];
    int tid = threadIdx.x, w = tid >> 5, lane = tid & 31;
    if (w < 3) {
        float s = 0.0f;
        for (int k = lane; k < N_H; k += 32)
            s += g_h[0][k] * dec_W[(size_t)w * (N_H + N_IN) + k];          // L even -> final in buf 0
        for (int k = lane; k < N_IN; k += 32)
            s += g_aemb[k] * dec_W[(size_t)w * (N_H + N_IN) + N_H + k];
        s = warp_sum(s);
        if (lane == 0) dec[w] = s + dec_b[w];
    }
    __syncthreads();
    for (int k = tid; k < out_size; k += blockDim.x) {
        float v = (k < 3) ? dec[k] : (k == 3 ? (float)g_retain : 0.0f);
        out[k] = v;
    }
}

// ------------------------- launch ------------------------------------------
extern "C" void kernel_launch(void* const* d_in, const int* in_sizes, int n_in,
                              void* d_out, int out_size) {
    const float*     inputs = (const float*)d_in[0];
    const long long* aspect = (const long long*)d_in[1];
    const float*     AE_w   = (const float*)d_in[2];
    const float*     W_ih   = (const float*)d_in[3];
    const float*     W_hh   = (const float*)d_in[4];
    const float*     b_ih   = (const float*)d_in[5];
    const float*     b_hh   = (const float*)d_in[6];
    const float*     dec_W  = (const float*)d_in[7];
    const float*     dec_b  = (const float*)d_in[8];
    const float*     pnet_W = (const float*)d_in[9];
    const float*     pnet_b = (const float*)d_in[10];

    k_init<<<64, 256>>>();
    k_aemb<<<1, 512>>>(aspect, AE_w, pnet_W, pnet_b);
    k_polbase<<<L_STEPS / 8, 256>>>(inputs, pnet_W);
    dim3 gg(N_G / GBN, L_STEPS / GBM);
    k_gemm<<<gg, 256>>>(inputs, W_ih, b_ih);
    k_seq<<<N_WORK + 1, 128>>>(W_hh, b_hh, pnet_W);
    k_final<<<1, 128>>>(dec_W, dec_b, (float*)d_out, out_size);
}